// round 10
// baseline (speedup 1.0000x reference)
#include <cuda_runtime.h>

// Segment-sum over sorted ray_indices + gather back.
// Output: d_out[0 .. n_rays*8)                    = per-ray sums
//         d_out[n_rays*8 .. n_rays*8+n_samples*8) = per-sample gathered sums
//
// Sorted indices => each ray is a contiguous pack.
//   1) boundary_kernel: streaming pass over idx -> pack offsets (static
//      __device__ scratch, no alloc).
//   2) fused raysum+scatter: one warp per ray. Flat predicated 5-deep load
//      batch (MLP=5, covers packs up to 80 samples ~ 98% of rays) + rare
//      remainder loop; parity-preserving butterfly; per-ray sum write +
//      broadcast scatter with flat predicated stores.

#define MAX_RAYS_PAD (1 << 20)
__device__ int g_off[MAX_RAYS_PAD + 1];

// ---------------- boundary kernel ----------------
#define BBLOCK 256
#define BRUN 32
#define B_SAMPLES (BBLOCK * BRUN)

__global__ void __launch_bounds__(BBLOCK)
boundary_kernel(const int* __restrict__ idx,
                int n_samples, int n_rays) {
    const int lane = threadIdx.x & 31;
    int base = (blockIdx.x * BBLOCK + threadIdx.x) * BRUN;
    const bool active = base < n_samples;
    int cnt = 0;

    int r[BRUN];
    if (active) {
        cnt = (base + BRUN <= n_samples) ? BRUN : (n_samples - base);
        if (cnt == BRUN) {
            const int4* p = reinterpret_cast<const int4*>(idx + base);
            #pragma unroll
            for (int q = 0; q < BRUN / 4; q++) {
                int4 v = p[q];
                r[q * 4 + 0] = v.x; r[q * 4 + 1] = v.y;
                r[q * 4 + 2] = v.z; r[q * 4 + 3] = v.w;
            }
        } else {
            for (int s = 0; s < BRUN; s++) r[s] = (s < cnt) ? idx[base + s] : 0;
        }
    } else {
        #pragma unroll
        for (int s = 0; s < BRUN; s++) r[s] = 0;
    }

    // prev = preceding thread's last element via shuffle; only lane 0 does a
    // scalar global load.
    int prev = __shfl_up_sync(0xFFFFFFFFu, r[BRUN - 1], 1);
    if (lane == 0) prev = (base == 0) ? -1 : (active ? idx[base - 1] : 0);
    if (!active) return;

    #pragma unroll
    for (int s = 0; s < BRUN; s++) {
        if (s >= cnt) break;
        if (r[s] != prev) {
            for (int q = prev + 1; q <= r[s]; q++) g_off[q] = base + s;
        }
        prev = r[s];
    }
    if (base + cnt == n_samples) {
        for (int q = prev + 1; q <= n_rays; q++) g_off[q] = n_samples;
    }
}

// ------- fused ray-sum + scatter kernel: one warp per ray -------
#define RSBLOCK 256
#define RAYS_PER_BLOCK (RSBLOCK / 32)
#define FLAT 5   // flat predicated batches (covers 80-sample packs)

__global__ void __launch_bounds__(RSBLOCK, 7)
raysum_scatter_kernel(const float4* __restrict__ vals,  // 2 float4 per sample
                      float4* __restrict__ sums,        // 2 float4 per ray
                      float4* __restrict__ out,         // 2 float4 per sample
                      int n_rays) {
    int warp = threadIdx.x >> 5;
    int lane = threadIdx.x & 31;
    int ray = blockIdx.x * RAYS_PER_BLOCK + warp;
    if (ray >= n_rays) return;

    // 32-bit indices: n_samples*2 = 8.4M fits comfortably.
    int a2 = g_off[ray] * 2;          // even -> lane parity == f4 parity
    int b2 = g_off[ray + 1] * 2;
    int j0 = a2 + lane;

    float4 acc0 = make_float4(0.f, 0.f, 0.f, 0.f);

    // Flat predicated batch: all FLAT loads issued back-to-back (MLP=FLAT),
    // no loop-carried dependency.
    {
        float4 v[FLAT];
        bool p[FLAT];
        #pragma unroll
        for (int k = 0; k < FLAT; k++) {
            p[k] = (j0 + k * 32) < b2;
            if (p[k]) v[k] = __ldcs(vals + j0 + k * 32);
        }
        #pragma unroll
        for (int k = 0; k < FLAT; k++) {
            if (p[k]) {
                acc0.x += v[k].x; acc0.y += v[k].y;
                acc0.z += v[k].z; acc0.w += v[k].w;
            }
        }
    }
    // Rare remainder (packs > 80 samples).
    for (int j = j0 + FLAT * 32; j < b2; j += 32) {
        float4 v = __ldcs(vals + j);
        acc0.x += v.x; acc0.y += v.y; acc0.z += v.z; acc0.w += v.w;
    }

    // Butterfly over even strides: every lane ends with the total for its
    // own parity (lane parity == float4-half parity).
    #pragma unroll
    for (int d = 2; d < 32; d <<= 1) {
        acc0.x += __shfl_xor_sync(0xFFFFFFFFu, acc0.x, d);
        acc0.y += __shfl_xor_sync(0xFFFFFFFFu, acc0.y, d);
        acc0.z += __shfl_xor_sync(0xFFFFFFFFu, acc0.z, d);
        acc0.w += __shfl_xor_sync(0xFFFFFFFFu, acc0.w, d);
    }

    // Per-ray sum: lane 0 holds half-0, lane 1 holds half-1.
    if (lane < 2) sums[ray * 2 + lane] = acc0;

    // Scatter the broadcast sum over the ray's contiguous output region.
    // out[j] parity == lane parity, so each lane stores its own acc0.
    #pragma unroll
    for (int k = 0; k < FLAT; k++) {
        if ((j0 + k * 32) < b2) __stcs(out + j0 + k * 32, acc0);
    }
    for (int j = j0 + FLAT * 32; j < b2; j += 32) __stcs(out + j, acc0);
}

extern "C" void kernel_launch(void* const* d_in, const int* in_sizes, int n_in,
                              void* d_out, int out_size) {
    const float4* vals = (const float4*)d_in[0];
    const int* idx = (const int*)d_in[1];

    int n_samples = in_sizes[1];                 // 4194304
    int n_rays = out_size / 8 - n_samples;       // 65536

    float4* sums = (float4*)d_out;                                    // [n_rays*2] float4
    float4* out_ps = (float4*)((float*)d_out + (size_t)n_rays * 8);   // [n_samples*2] float4

    // 1) ray pack offsets (one streaming pass over idx)
    {
        long long blocks = ((long long)n_samples + B_SAMPLES - 1) / B_SAMPLES;
        boundary_kernel<<<(unsigned)blocks, BBLOCK>>>(idx, n_samples, n_rays);
    }

    // 2) fused: one warp per ray -> sum + per-ray write + scatter write
    {
        long long blocks = ((long long)n_rays + RAYS_PER_BLOCK - 1) / RAYS_PER_BLOCK;
        raysum_scatter_kernel<<<(unsigned)blocks, RSBLOCK>>>(vals, sums, out_ps,
                                                             n_rays);
    }
}

// round 11
// speedup vs baseline: 1.0666x; 1.0666x over previous
#include <cuda_runtime.h>

// Segment-sum over sorted ray_indices + gather back.
// Output: d_out[0 .. n_rays*8)                    = per-ray sums
//         d_out[n_rays*8 .. n_rays*8+n_samples*8) = per-sample gathered sums
//
// Sorted indices => each ray is a contiguous pack.
//   1) boundary_kernel: streaming pass over idx -> pack offsets (static
//      __device__ scratch, no alloc).
//   2) fused raysum+scatter: one warp per ray, branch-uniform 4-deep load
//      loop (MLP=4), parity-preserving butterfly, per-ray sum write +
//      broadcast scatter. 32-bit indexing throughout.

#define MAX_RAYS_PAD (1 << 20)
__device__ int g_off[MAX_RAYS_PAD + 1];

// ---------------- boundary kernel ----------------
#define BBLOCK 256
#define BRUN 32
#define B_SAMPLES (BBLOCK * BRUN)

__global__ void __launch_bounds__(BBLOCK)
boundary_kernel(const int* __restrict__ idx,
                int n_samples, int n_rays) {
    const int lane = threadIdx.x & 31;
    int base = (blockIdx.x * BBLOCK + threadIdx.x) * BRUN;
    const bool active = base < n_samples;
    int cnt = 0;

    int r[BRUN];
    if (active) {
        cnt = (base + BRUN <= n_samples) ? BRUN : (n_samples - base);
        if (cnt == BRUN) {
            const int4* p = reinterpret_cast<const int4*>(idx + base);
            #pragma unroll
            for (int q = 0; q < BRUN / 4; q++) {
                int4 v = p[q];
                r[q * 4 + 0] = v.x; r[q * 4 + 1] = v.y;
                r[q * 4 + 2] = v.z; r[q * 4 + 3] = v.w;
            }
        } else {
            for (int s = 0; s < BRUN; s++) r[s] = (s < cnt) ? idx[base + s] : 0;
        }
    } else {
        #pragma unroll
        for (int s = 0; s < BRUN; s++) r[s] = 0;
    }

    // prev = preceding thread's last element via shuffle; only lane 0 does a
    // scalar global load.
    int prev = __shfl_up_sync(0xFFFFFFFFu, r[BRUN - 1], 1);
    if (lane == 0) prev = (base == 0) ? -1 : (active ? idx[base - 1] : 0);
    if (!active) return;

    #pragma unroll
    for (int s = 0; s < BRUN; s++) {
        if (s >= cnt) break;
        if (r[s] != prev) {
            for (int q = prev + 1; q <= r[s]; q++) g_off[q] = base + s;
        }
        prev = r[s];
    }
    if (base + cnt == n_samples) {
        for (int q = prev + 1; q <= n_rays; q++) g_off[q] = n_samples;
    }
}

// ------- fused ray-sum + scatter kernel: one warp per ray -------
#define RSBLOCK 256
#define RAYS_PER_BLOCK (RSBLOCK / 32)

__global__ void __launch_bounds__(RSBLOCK, 6)
raysum_scatter_kernel(const float4* __restrict__ vals,  // 2 float4 per sample
                      float4* __restrict__ sums,        // 2 float4 per ray
                      float4* __restrict__ out,         // 2 float4 per sample
                      int n_rays) {
    int warp = threadIdx.x >> 5;
    int lane = threadIdx.x & 31;
    int ray = blockIdx.x * RAYS_PER_BLOCK + warp;
    if (ray >= n_rays) return;

    // 32-bit indices: n_samples*2 = 8.4M fits comfortably.
    int a2 = g_off[ray] * 2;          // even -> lane parity == f4 parity
    int b2 = g_off[ray + 1] * 2;

    float4 acc0 = make_float4(0.f, 0.f, 0.f, 0.f);
    float4 acc1 = acc0;

    int j = a2 + lane;
    // Branch-uniform 4-deep loop: 4 independent LDG.128 in flight per iter
    // (mean pack = 128 float4 -> exactly one iteration), 2 accumulators.
    for (; j + 96 < b2; j += 128) {
        float4 v0 = __ldcs(vals + j);
        float4 v1 = __ldcs(vals + j + 32);
        float4 v2 = __ldcs(vals + j + 64);
        float4 v3 = __ldcs(vals + j + 96);
        acc0.x += v0.x; acc0.y += v0.y; acc0.z += v0.z; acc0.w += v0.w;
        acc1.x += v1.x; acc1.y += v1.y; acc1.z += v1.z; acc1.w += v1.w;
        acc0.x += v2.x; acc0.y += v2.y; acc0.z += v2.z; acc0.w += v2.w;
        acc1.x += v3.x; acc1.y += v3.y; acc1.z += v3.z; acc1.w += v3.w;
    }
    // Uniform remainder: one 2-deep step, then one single step.
    if (j + 32 < b2) {
        float4 v0 = __ldcs(vals + j);
        float4 v1 = __ldcs(vals + j + 32);
        acc0.x += v0.x; acc0.y += v0.y; acc0.z += v0.z; acc0.w += v0.w;
        acc1.x += v1.x; acc1.y += v1.y; acc1.z += v1.z; acc1.w += v1.w;
        j += 64;
    }
    if (j < b2) {
        float4 v = __ldcs(vals + j);
        acc0.x += v.x; acc0.y += v.y; acc0.z += v.z; acc0.w += v.w;
    }
    acc0.x += acc1.x; acc0.y += acc1.y; acc0.z += acc1.z; acc0.w += acc1.w;

    // Butterfly over even strides: every lane ends with the total for its
    // own parity (lane parity == float4-half parity).
    #pragma unroll
    for (int d = 2; d < 32; d <<= 1) {
        acc0.x += __shfl_xor_sync(0xFFFFFFFFu, acc0.x, d);
        acc0.y += __shfl_xor_sync(0xFFFFFFFFu, acc0.y, d);
        acc0.z += __shfl_xor_sync(0xFFFFFFFFu, acc0.z, d);
        acc0.w += __shfl_xor_sync(0xFFFFFFFFu, acc0.w, d);
    }

    // Per-ray sum: lane 0 holds half-0, lane 1 holds half-1.
    if (lane < 2) sums[ray * 2 + lane] = acc0;

    // Scatter the broadcast sum over the ray's contiguous output region.
    // out[j] parity == lane parity, so each lane stores its own acc0.
    j = a2 + lane;
    for (; j + 96 < b2; j += 128) {
        __stcs(out + j, acc0);
        __stcs(out + j + 32, acc0);
        __stcs(out + j + 64, acc0);
        __stcs(out + j + 96, acc0);
    }
    if (j + 32 < b2) {
        __stcs(out + j, acc0);
        __stcs(out + j + 32, acc0);
        j += 64;
    }
    if (j < b2) __stcs(out + j, acc0);
}

extern "C" void kernel_launch(void* const* d_in, const int* in_sizes, int n_in,
                              void* d_out, int out_size) {
    const float4* vals = (const float4*)d_in[0];
    const int* idx = (const int*)d_in[1];

    int n_samples = in_sizes[1];                 // 4194304
    int n_rays = out_size / 8 - n_samples;       // 65536

    float4* sums = (float4*)d_out;                                    // [n_rays*2] float4
    float4* out_ps = (float4*)((float*)d_out + (size_t)n_rays * 8);   // [n_samples*2] float4

    // 1) ray pack offsets (one streaming pass over idx)
    {
        long long blocks = ((long long)n_samples + B_SAMPLES - 1) / B_SAMPLES;
        boundary_kernel<<<(unsigned)blocks, BBLOCK>>>(idx, n_samples, n_rays);
    }

    // 2) fused: one warp per ray -> sum + per-ray write + scatter write
    {
        long long blocks = ((long long)n_rays + RAYS_PER_BLOCK - 1) / RAYS_PER_BLOCK;
        raysum_scatter_kernel<<<(unsigned)blocks, RSBLOCK>>>(vals, sums, out_ps,
                                                             n_rays);
    }
}

// round 12
// speedup vs baseline: 1.1604x; 1.0880x over previous
#include <cuda_runtime.h>

// Segment-sum over sorted ray_indices + gather back.
// Output: d_out[0 .. n_rays*8)                    = per-ray sums
//         d_out[n_rays*8 .. n_rays*8+n_samples*8) = per-sample gathered sums
//
// Sorted indices => each ray is a contiguous pack.
//   1) boundary_kernel: streaming pass over idx -> pack offsets (static
//      __device__ scratch, no alloc).
//   2) fused raysum+scatter: one warp per ray, branch-uniform 2-deep load
//      loop, parity-preserving butterfly, per-ray sum write + broadcast
//      scatter. 32-bit indexing; 32-reg / 8-blocks-per-SM occupancy target.

#define MAX_RAYS_PAD (1 << 20)
__device__ int g_off[MAX_RAYS_PAD + 1];

// ---------------- boundary kernel ----------------
#define BBLOCK 256
#define BRUN 16
#define B_SAMPLES (BBLOCK * BRUN)

__global__ void __launch_bounds__(BBLOCK)
boundary_kernel(const int* __restrict__ idx,
                int n_samples, int n_rays) {
    const int lane = threadIdx.x & 31;
    int base = (blockIdx.x * BBLOCK + threadIdx.x) * BRUN;
    const bool active = base < n_samples;
    int cnt = 0;

    int r[BRUN];
    if (active) {
        cnt = (base + BRUN <= n_samples) ? BRUN : (n_samples - base);
        if (cnt == BRUN) {
            const int4* p = reinterpret_cast<const int4*>(idx + base);
            #pragma unroll
            for (int q = 0; q < BRUN / 4; q++) {
                int4 v = p[q];
                r[q * 4 + 0] = v.x; r[q * 4 + 1] = v.y;
                r[q * 4 + 2] = v.z; r[q * 4 + 3] = v.w;
            }
        } else {
            for (int s = 0; s < BRUN; s++) r[s] = (s < cnt) ? idx[base + s] : 0;
        }
    } else {
        #pragma unroll
        for (int s = 0; s < BRUN; s++) r[s] = 0;
    }

    // prev = preceding thread's last element via shuffle; only lane 0 does a
    // scalar global load.
    int prev = __shfl_up_sync(0xFFFFFFFFu, r[BRUN - 1], 1);
    if (lane == 0) prev = (base == 0) ? -1 : (active ? idx[base - 1] : 0);
    if (!active) return;

    #pragma unroll
    for (int s = 0; s < BRUN; s++) {
        if (s >= cnt) break;
        if (r[s] != prev) {
            for (int q = prev + 1; q <= r[s]; q++) g_off[q] = base + s;
        }
        prev = r[s];
    }
    if (base + cnt == n_samples) {
        for (int q = prev + 1; q <= n_rays; q++) g_off[q] = n_samples;
    }
}

// ------- fused ray-sum + scatter kernel: one warp per ray -------
#define RSBLOCK 256
#define RAYS_PER_BLOCK (RSBLOCK / 32)

__global__ void __launch_bounds__(RSBLOCK, 8)
raysum_scatter_kernel(const float4* __restrict__ vals,  // 2 float4 per sample
                      float4* __restrict__ sums,        // 2 float4 per ray
                      float4* __restrict__ out,         // 2 float4 per sample
                      int n_rays) {
    int warp = threadIdx.x >> 5;
    int lane = threadIdx.x & 31;
    int ray = blockIdx.x * RAYS_PER_BLOCK + warp;
    if (ray >= n_rays) return;

    // 32-bit indices: n_samples*2 = 8.4M fits comfortably.
    int a2 = g_off[ray] * 2;          // even -> lane parity == f4 parity
    int b2 = g_off[ray + 1] * 2;

    float4 acc0 = make_float4(0.f, 0.f, 0.f, 0.f);
    float4 acc1 = acc0;

    int j = a2 + lane;
    // Branch-uniform 2-deep loop (mean pack = 128 f4 -> ~2 iters).
    for (; j + 32 < b2; j += 64) {
        float4 v0 = __ldcs(vals + j);
        float4 v1 = __ldcs(vals + j + 32);
        acc0.x += v0.x; acc0.y += v0.y; acc0.z += v0.z; acc0.w += v0.w;
        acc1.x += v1.x; acc1.y += v1.y; acc1.z += v1.z; acc1.w += v1.w;
    }
    if (j < b2) {
        float4 v = __ldcs(vals + j);
        acc0.x += v.x; acc0.y += v.y; acc0.z += v.z; acc0.w += v.w;
    }
    acc0.x += acc1.x; acc0.y += acc1.y; acc0.z += acc1.z; acc0.w += acc1.w;

    // Butterfly over even strides: every lane ends with the total for its
    // own parity (lane parity == float4-half parity).
    #pragma unroll
    for (int d = 2; d < 32; d <<= 1) {
        acc0.x += __shfl_xor_sync(0xFFFFFFFFu, acc0.x, d);
        acc0.y += __shfl_xor_sync(0xFFFFFFFFu, acc0.y, d);
        acc0.z += __shfl_xor_sync(0xFFFFFFFFu, acc0.z, d);
        acc0.w += __shfl_xor_sync(0xFFFFFFFFu, acc0.w, d);
    }

    // Per-ray sum: lane 0 holds half-0, lane 1 holds half-1.
    if (lane < 2) sums[ray * 2 + lane] = acc0;

    // Scatter the broadcast sum over the ray's contiguous output region.
    // out[j] parity == lane parity, so each lane stores its own acc0.
    j = a2 + lane;
    for (; j + 32 < b2; j += 64) {
        __stcs(out + j, acc0);
        __stcs(out + j + 32, acc0);
    }
    if (j < b2) __stcs(out + j, acc0);
}

extern "C" void kernel_launch(void* const* d_in, const int* in_sizes, int n_in,
                              void* d_out, int out_size) {
    const float4* vals = (const float4*)d_in[0];
    const int* idx = (const int*)d_in[1];

    int n_samples = in_sizes[1];                 // 4194304
    int n_rays = out_size / 8 - n_samples;       // 65536

    float4* sums = (float4*)d_out;                                    // [n_rays*2] float4
    float4* out_ps = (float4*)((float*)d_out + (size_t)n_rays * 8);   // [n_samples*2] float4

    // 1) ray pack offsets (one streaming pass over idx)
    {
        long long blocks = ((long long)n_samples + B_SAMPLES - 1) / B_SAMPLES;
        boundary_kernel<<<(unsigned)blocks, BBLOCK>>>(idx, n_samples, n_rays);
    }

    // 2) fused: one warp per ray -> sum + per-ray write + scatter write
    {
        long long blocks = ((long long)n_rays + RAYS_PER_BLOCK - 1) / RAYS_PER_BLOCK;
        raysum_scatter_kernel<<<(unsigned)blocks, RSBLOCK>>>(vals, sums, out_ps,
                                                             n_rays);
    }
}